// round 14
// baseline (speedup 1.0000x reference)
#include <cuda_runtime.h>
#include <math.h>

#define NK     10000
#define SEQ    512
#define XS_POS 1536                      // genuine reads <= 1533; over-reads clamped
#define SMEM_BYTES (XS_POS * 8 * 4)      // 49152 B dynamic shared
#define NT     448
#define NBLK   444                       // 3 CTAs/SM * 148 SMs, all resident
#define TOTAL_WARPS (NBLK * (NT / 32))   // 6216
#define IDX_MAX 3070                     // float4-index clamp (pos 1535, h=1 -> 3071)

__device__ int g_ctr;                    // work-steal cursor (self-resetting)
__device__ int g_done;                   // finished-warp count (self-resetting)

// Process rocket conv-kernel i with compile-time tap count K, tile height M=5.
// Lanes: c = lane>>1 (16 tile-lanes), h = lane&1 (batch half). Tile = M chain-
// consecutive outputs t0..t0+(M-1)d sharing K+M-1 float4 loads.
// Conflict-free (no swizzle): M=5 => within each 8-lane phase the four
// consecutive tile-indices give t0 mod 4 all-distinct for every dilation.
// Over-reads past the genuine range are clamped to IDX_MAX; they only feed
// accumulators whose outputs t >= lo, which are discarded.
// Accumulates s' = -s: max s = -min s'; ppv counts via PRMT sign-byte gather.
template<int K, int M>
static __device__ __forceinline__ void process_i(
    const float4* __restrict__ xsf, int i, int c, int h,
    const float* __restrict__ w, float bias, int dil, int lo, int pad,
    float* __restrict__ out)
{
    float wn[K];
#pragma unroll
    for (int j = 0; j < K; ++j) wn[j] = -w[j];
    const float biasn = -bias;

    const int dM = dil * M;
    const int stripes = (lo + dM - 1) / dM;            // once per item, warp-uniform
    const int ntiles = stripes * dil;
    const float inv_d = 1.0f / (float)dil;
    const int inc = dil * 2;                           // float4-index step per tap
    const int base0 = (SEQ - pad) * 2 + h;

    float mn0 = INFINITY, mn1 = INFINITY, mn2 = INFINITY, mn3 = INFINITY;
    unsigned c4 = 0u;                                  // 4x8-bit per-batch sign counts

    for (int j = c; j < ntiles; j += 16) {
        // (stripe, off) = (j / dil, j % dil) via float reciprocal + correction
        int stripe = __float2int_rd(__int2float_rn(j) * inv_d);
        int off = j - stripe * dil;
        if (off < 0)         { --stripe; off += dil; }
        else if (off >= dil) { ++stripe; off -= dil; }
        const int t0 = stripe * dM + off;
        if (t0 >= lo) continue;

        int idx = base0 + t0 * 2;
        float a0[M], a1[M], a2[M], a3[M];
#pragma unroll
        for (int q = 0; q < M; ++q) { a0[q] = biasn; a1[q] = biasn; a2[q] = biasn; a3[q] = biasn; }

#pragma unroll
        for (int v = 0; v < K + M - 1; ++v) {
            const int idxc = min(idx, IDX_MAX);        // over-read clamp (exact; see header)
            const float4 L = xsf[idxc];
#pragma unroll
            for (int q = 0; q < M; ++q) {
                const int jj = v - q;
                if (jj >= 0 && jj < K) {
                    a0[q] = fmaf(wn[jj], L.x, a0[q]);
                    a1[q] = fmaf(wn[jj], L.y, a1[q]);
                    a2[q] = fmaf(wn[jj], L.z, a2[q]);
                    a3[q] = fmaf(wn[jj], L.w, a3[q]);
                }
            }
            idx += inc;
        }

#pragma unroll
        for (int q = 0; q < M; ++q) {
            if (t0 + q * dil < lo) {
                mn0 = fminf(mn0, a0[q]);
                mn1 = fminf(mn1, a1[q]);
                mn2 = fminf(mn2, a2[q]);
                mn3 = fminf(mn3, a3[q]);
                // gather the 4 sign bytes (byte3 of each f32) into one word
                unsigned t1 = __byte_perm(__float_as_uint(a0[q]), __float_as_uint(a1[q]), 0x0073);
                unsigned t2 = __byte_perm(__float_as_uint(a2[q]), __float_as_uint(a3[q]), 0x7300);
                unsigned tm = __byte_perm(t1, t2, 0x7610);   // [s0, s1, s2, s3]
                c4 += (tm >> 7) & 0x01010101u;
            }
        }
    }

    // reduce across the 16 tile-lanes (xor 2..16 keeps h fixed);
    // counts unpacked to 2x16-bit (sums <= 1022, no carry)
    unsigned p01 = __byte_perm(c4, 0u, 0x4140);        // cnt0 | cnt1<<16
    unsigned p23 = __byte_perm(c4, 0u, 0x4342);        // cnt2 | cnt3<<16
#pragma unroll
    for (int off = 2; off < 32; off <<= 1) {
        mn0 = fminf(mn0, __shfl_xor_sync(0xffffffffu, mn0, off));
        mn1 = fminf(mn1, __shfl_xor_sync(0xffffffffu, mn1, off));
        mn2 = fminf(mn2, __shfl_xor_sync(0xffffffffu, mn2, off));
        mn3 = fminf(mn3, __shfl_xor_sync(0xffffffffu, mn3, off));
        p01 += __shfl_xor_sync(0xffffffffu, p01, off);
        p23 += __shfl_xor_sync(0xffffffffu, p23, off);
    }

    if (c == 0) {
        const float il = 1.f / (float)lo;
        float2* o2 = reinterpret_cast<float2*>(out);
        o2[(4 * h + 0) * NK + i] = make_float2(-mn0, (float)(p01 & 0xFFFFu) * il);
        o2[(4 * h + 1) * NK + i] = make_float2(-mn1, (float)(p01 >> 16) * il);
        o2[(4 * h + 2) * NK + i] = make_float2(-mn2, (float)(p23 & 0xFFFFu) * il);
        o2[(4 * h + 3) * NK + i] = make_float2(-mn3, (float)(p23 >> 16) * il);
    }
}

__global__ __launch_bounds__(NT, 3)
void rocket_kernel(const float* __restrict__ x,     // (8,1,512)
                   const float* __restrict__ W,     // (10000,1,11)
                   const float* __restrict__ Bias,  // (10000,)
                   const int*   __restrict__ dil_,  // (10000,)
                   const int*   __restrict__ lo_,   // (10000,)
                   float*       __restrict__ out)   // (8, 20000) interleaved (max, ppv)
{
    extern __shared__ float xs[];   // plain [pos][8 batches] layout, zero-padded
    const int tid = threadIdx.x;

    // Prologue (single barrier): zero the two pad regions, transpose x into the
    // middle. Disjoint float4 ranges: zeros [0,1024)+[2048,3072), x [1024,2048).
    float4* z4 = reinterpret_cast<float4*>(xs);
    for (int t = tid; t < 1024; t += NT)
        z4[t] = make_float4(0.f, 0.f, 0.f, 0.f);
    for (int t = tid; t < 1024; t += NT)
        z4[2048 + t] = make_float4(0.f, 0.f, 0.f, 0.f);
    for (int t = tid; t < 8 * SEQ; t += NT) {
        int b = t >> 9;
        int s = t & 511;
        xs[(s + SEQ) * 8 + b] = x[t];
    }
    __syncthreads();

    const int lane = tid & 31;
    const int c = lane >> 1;
    const int h = lane & 1;
    const float4* xsf = reinterpret_cast<const float4*>(xs);

    while (true) {
        int i;
        if (lane == 0) i = atomicAdd(&g_ctr, 1);
        i = __shfl_sync(0xffffffffu, i, 0);
        if (i >= NK) break;

        float w[11];
        const float* wr = W + i * 11;
#pragma unroll
        for (int j = 0; j < 11; ++j) w[j] = __ldg(wr + j);
        const float bias = __ldg(Bias + i);
        const int   dil  = __ldg(dil_ + i);
        const int   lo   = __ldg(lo_ + i);

        // recover tap count from exact-zero weight tail; M=5 for all K
        if (w[7] == 0.f && w[8] == 0.f) {
            const int pad = (lo - SEQ + dil * 6) >> 1;
            process_i<7, 5>(xsf, i, c, h, w, bias, dil, lo, pad, out);
        } else if (w[9] == 0.f && w[10] == 0.f) {
            const int pad = (lo - SEQ + dil * 8) >> 1;
            process_i<9, 5>(xsf, i, c, h, w, bias, dil, lo, pad, out);
        } else {
            const int pad = (lo - SEQ + dil * 10) >> 1;
            process_i<11, 5>(xsf, i, c, h, w, bias, dil, lo, pad, out);
        }
    }

    // Self-resetting counters: a warp increments g_done only after its final
    // g_ctr atomic, so the last arrival implies all steals are done. Kernel
    // completion fences the stores for the next graph replay.
    if (lane == 0) {
        int d = atomicAdd(&g_done, 1);
        if (d == TOTAL_WARPS - 1) {
            g_ctr = 0;
            g_done = 0;
        }
    }
}

extern "C" void kernel_launch(void* const* d_in, const int* in_sizes, int n_in,
                              void* d_out, int out_size) {
    const float* x    = (const float*)d_in[0];  // (8,1,512)
    const float* Wt   = (const float*)d_in[1];  // (10000,1,11)
    const float* Bias = (const float*)d_in[2];  // (10000,)
    // d_in[3] = base (unused: pad recovered from lo/dil/k)
    const int*   dil  = (const int*)d_in[4];
    const int*   lo   = (const int*)d_in[5];
    float* out = (float*)d_out;                 // (8, 20000)

    cudaFuncSetAttribute(rocket_kernel,
                         cudaFuncAttributeMaxDynamicSharedMemorySize, SMEM_BYTES);
    rocket_kernel<<<NBLK, NT, SMEM_BYTES>>>(x, Wt, Bias, dil, lo, out);
}

// round 15
// speedup vs baseline: 1.1714x; 1.1714x over previous
#include <cuda_runtime.h>
#include <math.h>

#define NK     10000
#define SEQ    512
#define XS_POS 1792                      // worst read: K7/M5 guarded<=1791; K9/M5<=1787; K11/M4<=1686
#define SMEM_BYTES (XS_POS * 8 * 4)      // 57344 B dynamic shared; 3 CTAs/SM = 172KB <= 228KB
#define NT     384
#define NBLK   444                       // 3 CTAs/SM * 148 SMs, all resident (36 warps/SM)
#define TOTAL_WARPS (NBLK * (NT / 32))   // 5328

typedef unsigned long long ull;

__device__ int g_ctr;                    // work-steal cursor (self-resetting)
__device__ int g_done;                   // finished-warp count (self-resetting)

static __device__ __forceinline__ ull pack2(float a, float b) {
    ull r; asm("mov.b64 %0, {%1, %2};" : "=l"(r) : "f"(a), "f"(b)); return r;
}
static __device__ __forceinline__ ull fma2(ull a, ull b, ull c) {
    ull r; asm("fma.rn.f32x2 %0, %1, %2, %3;" : "=l"(r) : "l"(a), "l"(b), "l"(c)); return r;
}
static __device__ __forceinline__ unsigned lo32(ull v) { return (unsigned)v; }
static __device__ __forceinline__ unsigned hi32(ull v) { return (unsigned)(v >> 32); }

// Process rocket conv-kernel i with compile-time tap count K, tile height M.
// Lanes: c = lane>>1 (16 tile-lanes), h = lane&1 (batch half). Tile = M chain-
// consecutive outputs t0..t0+(M-1)d sharing K+M-1 loads.
// NO SWIZZLE: for M=5, t0 ≡ j (mod 4) for every d => each quarter-warp's idx
// values are distinct mod 8 => conflict-free LDS.128. (M=4/M=3 paths rely on
// the same property only partially; they are the rare/cold cases.)
// Accumulates s' = -s: max s = -min s'; ppv counts gathered as sign bytes via
// PRMT into one 4x8-bit counter (per-lane per-batch count <= 64 < 255).
// SAFETY: caller guarantees pad + (M-1)*dil <= 768 so all reads < XS_POS.
template<int K, int M>
static __device__ __forceinline__ void process_i(
    const ulonglong2* __restrict__ xsu, int i, int c, int h,
    const float* __restrict__ w, float bias, int dil, int lo, int pad,
    float* __restrict__ out)
{
    ull wn[K];
#pragma unroll
    for (int j = 0; j < K; ++j) wn[j] = pack2(-w[j], -w[j]);
    const ull biasn = pack2(-bias, -bias);

    const int dM = dil * M;
    const int stripes = (lo + dM - 1) / dM;            // once per item, warp-uniform
    const int ntiles = stripes * dil;
    const float inv_d = 1.0f / (float)dil;
    const int inc = dil * 2;                           // ulonglong2-index step per tap
    const int base0 = (SEQ - pad) * 2 + h;

    float mn0 = INFINITY, mn1 = INFINITY, mn2 = INFINITY, mn3 = INFINITY;
    unsigned c4 = 0u;                                  // 4x8-bit per-batch sign counts

    for (int j = c; j < ntiles; j += 16) {
        // (stripe, off) = (j / dil, j % dil) via float reciprocal + correction
        int stripe = __float2int_rd(__int2float_rn(j) * inv_d);
        int off = j - stripe * dil;
        if (off < 0)         { --stripe; off += dil; }
        else if (off >= dil) { ++stripe; off -= dil; }
        const int t0 = stripe * dM + off;
        if (t0 >= lo) continue;

        int idx = base0 + t0 * 2;
        ull aL[M], aH[M];
#pragma unroll
        for (int q = 0; q < M; ++q) { aL[q] = biasn; aH[q] = biasn; }

#pragma unroll
        for (int v = 0; v < K + M - 1; ++v) {
            const ulonglong2 L = xsu[idx];             // no swizzle
#pragma unroll
            for (int q = 0; q < M; ++q) {
                const int jj = v - q;
                if (jj >= 0 && jj < K) {
                    aL[q] = fma2(wn[jj], L.x, aL[q]);
                    aH[q] = fma2(wn[jj], L.y, aH[q]);
                }
            }
            idx += inc;
        }

#pragma unroll
        for (int q = 0; q < M; ++q) {
            if (t0 + q * dil < lo) {
                const unsigned u0 = lo32(aL[q]), u1 = hi32(aL[q]);
                const unsigned u2 = lo32(aH[q]), u3 = hi32(aH[q]);
                mn0 = fminf(mn0, __uint_as_float(u0));
                mn1 = fminf(mn1, __uint_as_float(u1));
                mn2 = fminf(mn2, __uint_as_float(u2));
                mn3 = fminf(mn3, __uint_as_float(u3));
                // gather the 4 sign bytes (byte3 of each f32) into one word
                unsigned t1 = __byte_perm(u0, u1, 0x0073);   // [s0, s1, 0, 0]
                unsigned t2 = __byte_perm(u2, u3, 0x7300);   // [0, 0, s2, s3]
                unsigned tm = __byte_perm(t1, t2, 0x7610);   // [s0, s1, s2, s3]
                c4 += (tm >> 7) & 0x01010101u;
            }
        }
    }

    // reduce across the 16 tile-lanes (xor 2..16 keeps h fixed);
    // counts unpacked to 2x16-bit (sums <= 1022, no carry)
    unsigned p01 = __byte_perm(c4, 0u, 0x4140);        // cnt0 | cnt1<<16
    unsigned p23 = __byte_perm(c4, 0u, 0x4342);        // cnt2 | cnt3<<16
#pragma unroll
    for (int off = 2; off < 32; off <<= 1) {
        mn0 = fminf(mn0, __shfl_xor_sync(0xffffffffu, mn0, off));
        mn1 = fminf(mn1, __shfl_xor_sync(0xffffffffu, mn1, off));
        mn2 = fminf(mn2, __shfl_xor_sync(0xffffffffu, mn2, off));
        mn3 = fminf(mn3, __shfl_xor_sync(0xffffffffu, mn3, off));
        p01 += __shfl_xor_sync(0xffffffffu, p01, off);
        p23 += __shfl_xor_sync(0xffffffffu, p23, off);
    }

    if (c == 0) {
        const float il = 1.f / (float)lo;
        float2* o2 = reinterpret_cast<float2*>(out);
        o2[(4 * h + 0) * NK + i] = make_float2(-mn0, (float)(p01 & 0xFFFFu) * il);
        o2[(4 * h + 1) * NK + i] = make_float2(-mn1, (float)(p01 >> 16) * il);
        o2[(4 * h + 2) * NK + i] = make_float2(-mn2, (float)(p23 & 0xFFFFu) * il);
        o2[(4 * h + 3) * NK + i] = make_float2(-mn3, (float)(p23 >> 16) * il);
    }
}

__global__ __launch_bounds__(NT, 3)
void rocket_kernel(const float* __restrict__ x,     // (8,1,512)
                   const float* __restrict__ W,     // (10000,1,11)
                   const float* __restrict__ Bias,  // (10000,)
                   const int*   __restrict__ dil_,  // (10000,)
                   const int*   __restrict__ lo_,   // (10000,)
                   float*       __restrict__ out)   // (8, 20000) interleaved (max, ppv)
{
    extern __shared__ float xs[];   // plain [pos][8 batches] layout, zero-padded
    const int tid = threadIdx.x;

    // Prologue (single barrier): zero the two pad regions, transpose x into the
    // middle. Disjoint float4 ranges: zeros [0,1024)+[2048,3584), x [1024,2048).
    float4* z4 = reinterpret_cast<float4*>(xs);
    for (int t = tid; t < 1024; t += NT)
        z4[t] = make_float4(0.f, 0.f, 0.f, 0.f);
    for (int t = tid; t < 1536; t += NT)
        z4[2048 + t] = make_float4(0.f, 0.f, 0.f, 0.f);
    for (int t = tid; t < 8 * SEQ; t += NT) {
        int b = t >> 9;
        int s = t & 511;
        xs[(s + SEQ) * 8 + b] = x[t];
    }
    __syncthreads();

    const int lane = tid & 31;
    const int c = lane >> 1;
    const int h = lane & 1;
    const ulonglong2* xsu = reinterpret_cast<const ulonglong2*>(xs);

    while (true) {
        int i;
        if (lane == 0) i = atomicAdd(&g_ctr, 1);
        i = __shfl_sync(0xffffffffu, i, 0);
        if (i >= NK) break;

        float w[11];
        const float* wr = W + i * 11;
#pragma unroll
        for (int j = 0; j < 11; ++j) w[j] = __ldg(wr + j);
        const float bias = __ldg(Bias + i);
        const int   dil  = __ldg(dil_ + i);
        const int   lo   = __ldg(lo_ + i);

        // recover tap count from exact-zero weight tail
        if (w[7] == 0.f && w[8] == 0.f) {
            const int pad = (lo - SEQ + dil * 6) >> 1;
            if (pad + 4 * dil <= 768)
                process_i<7, 5>(xsu, i, c, h, w, bias, dil, lo, pad, out);
            else
                process_i<7, 3>(xsu, i, c, h, w, bias, dil, lo, pad, out);
        } else if (w[9] == 0.f && w[10] == 0.f) {
            const int pad = (lo - SEQ + dil * 8) >> 1;   // M=5: pad+4d <= 764 always
            process_i<9, 5>(xsu, i, c, h, w, bias, dil, lo, pad, out);
        } else {
            const int pad = (lo - SEQ + dil * 10) >> 1;  // M=4: pad+3d <= 663 always
            process_i<11, 4>(xsu, i, c, h, w, bias, dil, lo, pad, out);
        }
    }

    // Self-resetting counters: a warp increments g_done only after its final
    // g_ctr atomic, so the last arrival implies all steals are done. Kernel
    // completion fences the stores for the next graph replay.
    if (lane == 0) {
        int d = atomicAdd(&g_done, 1);
        if (d == TOTAL_WARPS - 1) {
            g_ctr = 0;
            g_done = 0;
        }
    }
}

extern "C" void kernel_launch(void* const* d_in, const int* in_sizes, int n_in,
                              void* d_out, int out_size) {
    const float* x    = (const float*)d_in[0];  // (8,1,512)
    const float* Wt   = (const float*)d_in[1];  // (10000,1,11)
    const float* Bias = (const float*)d_in[2];  // (10000,)
    // d_in[3] = base (unused: pad recovered from lo/dil/k)
    const int*   dil  = (const int*)d_in[4];
    const int*   lo   = (const int*)d_in[5];
    float* out = (float*)d_out;                 // (8, 20000)

    cudaFuncSetAttribute(rocket_kernel,
                         cudaFuncAttributeMaxDynamicSharedMemorySize, SMEM_BYTES);
    rocket_kernel<<<NBLK, NT, SMEM_BYTES>>>(x, Wt, Bias, dil, lo, out);
}